// round 6
// baseline (speedup 1.0000x reference)
#include <cuda_runtime.h>

#define NN 4096
#define TT 3
#define DD 20
#define EE 131072      // 2^17
#define ATT_DIM 128
#define HEADS 2
#define LAYERS 2
#define WPR 128        // 32-bit words per bitmap row (4096/32)
#define NEG 0.2f
#define MAXDEG 384     // mean degree ~186, huge sigma headroom; MAXDEG/2 = 6*32
#define L2E 1.4426950408889634f

#define SCAT_BLKS 1536           // TT*EE / 256
#define SCORE_BLKS 512           // 4096 rows / 8 warps
#define PREP_BLKS (SCAT_BLKS + SCORE_BLKS + 1)
#define PASS_BLKS 128            // single wave: 32 rows/block

// ---- device scratch (static, allocation-free) ----
// interleaved bitmaps: [row][word][4] (lane 3 pad) -> one LDG.128 in build.
// Starts zeroed (.bss); k_build re-zeroes after reading -> invariant holds
// across graph replays without a dedicated zeroing kernel.
__device__ __align__(16) unsigned       g_bmi[NN * WPR * 4];   // 8MB
__device__ __align__(16) unsigned short g_ent[NN * MAXDEG];    // j | (m<<12)
__device__ int    g_cnt[NN];                                   // even (padded)
__device__ __align__(16) float g_s0[NN];
__device__ __align__(16) float g_s1[NN];
__device__ float  g_S[2];
__device__ float4 g_tab[LAYERS][8];   // per-mask: (lut_h0', lut_h1', M, _)
__device__ float  g_ab[LAYERS][4];    // a0', b0', a1', b1' (log2e folded)
__device__ unsigned g_ticket = 0;

__device__ __forceinline__ float ex2f(float x) {
    float r;
    asm("ex2.approx.ftz.f32 %0, %1;" : "=f"(r) : "f"(x));
    return r;
}

// ----------------------- fused: edge scatter + initial scores + constants + S0
__global__ void __launch_bounds__(256) k_prep(const int* __restrict__ el,
                                              const float* __restrict__ inputs,
                                              const float* __restrict__ lw,
                                              const float* __restrict__ lb,
                                              const float* __restrict__ edge_emb,
                                              const float* __restrict__ att_w) {
    __shared__ unsigned win;
    __shared__ float    red[256];
    int bid = blockIdx.x, tid = threadIdx.x;

    if (bid < SCAT_BLKS) {
        // ---- edge scatter: i < TT*EE
        int i = bid * 256 + tid;
        int t = i >> 17;               // EE = 2^17
        int e = i & (EE - 1);
        int s = el[(t * 2 + 0) * EE + e];
        int g = el[(t * 2 + 1) * EE + e];
        atomicOr(&g_bmi[(s * WPR + (g >> 5)) * 4 + t], 1u << (g & 31));
        atomicOr(&g_bmi[(g * WPR + (s >> 5)) * 4 + t], 1u << (s & 31));
    } else if (bid < SCAT_BLKS + SCORE_BLKS) {
        // ---- initial linear scores: one row per warp, 8 warps
        int warp = tid >> 5, lane = tid & 31;
        int row  = (bid - SCAT_BLKS) * 8 + warp;
        float4 v = reinterpret_cast<const float4*>(inputs + row * ATT_DIM)[lane];
        float4 w = reinterpret_cast<const float4*>(lw)[lane];
        float acc = v.x * w.x + v.y * w.y + v.z * w.z + v.w * w.w;
        #pragma unroll
        for (int o = 16; o; o >>= 1) acc += __shfl_xor_sync(0xFFFFFFFFu, acc, o);
        if (lane == 0) g_s0[row] = acc + lb[0];
    } else {
        // ---- per-(layer,head) constants
        float* tabf = reinterpret_cast<float*>(&g_tab[0][0]);
        if (tid < LAYERS * HEADS) {
            int l = tid >> 1, h = tid & 1;
            const float* w = att_w + (l * HEADS + h) * (DD + 2);
            float et[TT];
            #pragma unroll
            for (int t = 0; t < TT; t++) {
                float acc = 0.0f;
                #pragma unroll
                for (int d = 0; d < DD; d++) acc += edge_emb[t * DD + d] * w[1 + d];
                et[t] = acc * L2E;
            }
            g_ab[l][h * 2 + 0] = w[0] * L2E;
            g_ab[l][h * 2 + 1] = w[DD + 1] * L2E;
            #pragma unroll
            for (int m = 0; m < 8; m++) {
                float B = 0.0f;
                #pragma unroll
                for (int t = 0; t < TT; t++) if ((m >> t) & 1) B += et[t];
                tabf[(l * 8 + m) * 4 + h] = B;
            }
        } else if (tid < LAYERS * HEADS + 2) {
            int l = tid - LAYERS * HEADS;
            #pragma unroll
            for (int m = 0; m < 8; m++)
                tabf[(l * 8 + m) * 4 + 2] = (float)__popc((unsigned)m);
        }
    }

    // ---- last-retiring block computes S0 (deterministic fixed-order tree)
    __threadfence();
    __syncthreads();
    if (tid == 0) win = (atomicAdd(&g_ticket, 1u) == (unsigned)(gridDim.x - 1));
    __syncthreads();
    if (win) {
        if (tid == 0) g_ticket = 0;
        __threadfence();
        float p = 0.0f;
        #pragma unroll
        for (int i = tid; i < NN; i += 256) p += __ldcg(&g_s0[i]);
        red[tid] = p;
        __syncthreads();
        #pragma unroll
        for (int o = 128; o; o >>= 1) {
            if (tid < o) red[tid] += red[tid + o];
            __syncthreads();
        }
        if (tid == 0) g_S[0] = red[0];
    }
}

// ------------------------------------------------- bitmap -> packed CSR (once)
// one block per row, one 32-bit word per thread; smem-staged coalesced writeout.
// Also restores g_bmi to zero for the next graph replay.
__global__ void __launch_bounds__(128) k_build() {
    __shared__ int wsum[4];
    __shared__ int stot;
    __shared__ __align__(16) unsigned short se[MAXDEG];
    int row  = blockIdx.x;
    int tid  = threadIdx.x;
    int warp = tid >> 5, lane = tid & 31;

    // zero staging row (MAXDEG u16 = 192 u32)
    reinterpret_cast<unsigned*>(se)[tid] = 0;
    if (tid < 64) reinterpret_cast<unsigned*>(se)[tid + 128] = 0;

    uint4* bp = reinterpret_cast<uint4*>(&g_bmi[0]) + row * WPR + tid;
    uint4 w = *bp;
    *bp = make_uint4(0u, 0u, 0u, 0u);        // restore zero invariant
    unsigned w0 = w.x, w1 = w.y, w2 = w.z;
    unsigned u  = w0 | w1 | w2;
    int cnt = __popc(u);

    int inc = cnt;                           // inclusive warp scan
    #pragma unroll
    for (int o = 1; o < 32; o <<= 1) {
        int n = __shfl_up_sync(0xFFFFFFFFu, inc, o);
        if (lane >= o) inc += n;
    }
    if (lane == 31) wsum[warp] = inc;
    __syncthreads();                          // also orders se zeroing

    int base = inc - cnt;                     // exclusive within warp
    #pragma unroll
    for (int ww = 0; ww < 3; ww++) if (ww < warp) base += wsum[ww];

    int col = tid * 32;
    while (u) {
        int b = __ffs(u) - 1;
        u &= u - 1;
        int m = ((w0 >> b) & 1) | (((w1 >> b) & 1) << 1) | (((w2 >> b) & 1) << 2);
        se[base++] = (unsigned short)((col + b) | (m << 12));
    }

    if (tid == 127) {                         // warp3 lane31: inc == warp3 total
        int tot = wsum[0] + wsum[1] + wsum[2] + inc;
        tot = (tot + 1) & ~1;                 // pad slot already zeroed
        stot = tot;
        g_cnt[row] = tot;
    }
    __syncthreads();

    // coalesced writeout: 48 uint4 = 384 u16
    if (tid < MAXDEG * 2 / 16)
        reinterpret_cast<uint4*>(&g_ent[row * MAXDEG])[tid] =
            reinterpret_cast<const uint4*>(se)[tid];
    (void)stot;
}

// ------------------------------------- attention pass (one layer, both heads)
// 128 blocks x 1024 threads: single wave, 32 rows/block (one per warp).
// Entry stream prefetched with MLP=6. Layer 0 epilogue reduces S1.
__global__ void __launch_bounds__(1024) k_pass(int layer, float* __restrict__ out_ext) {
    __shared__ float  ss[NN];          // 16KB: all scores
    __shared__ float4 tab[8];
    __shared__ float  ab[4];
    __shared__ unsigned win;
    __shared__ float  red[32];

    const float* __restrict__ sp = (layer == 0) ? g_s0 : g_s1;
    float* __restrict__ outp     = (layer == 0) ? g_s1 : out_ext;

    int tid  = threadIdx.x;
    int warp = tid >> 5, lane = tid & 31;
    int row  = blockIdx.x * 32 + warp;

    int cnt = g_cnt[row];                               // overlap with staging
    const unsigned* __restrict__ ep32 =
        reinterpret_cast<const unsigned*>(&g_ent[row * MAXDEG]);
    unsigned pr[6];
    #pragma unroll
    for (int q = 0; q < 6; q++) pr[q] = ep32[lane + q * 32];   // MLP=6 prefetch

    // stage all scores: one float4 per thread
    reinterpret_cast<float4*>(ss)[tid] =
        __ldcg(reinterpret_cast<const float4*>(sp) + tid);
    if (tid < 8)       tab[tid]    = g_tab[layer][tid];
    else if (tid < 12) ab[tid - 8] = g_ab[layer][tid - 8];
    __syncthreads();

    float S  = g_S[layer];
    float si = ss[row];
    float a0 = ab[0], b0 = ab[1], a1 = ab[2], b1 = ab[3];
    float c0 = a0 * si, c1 = a1 * si;

    int nit = cnt >> 1;          // u32 pairs
    float e0 = 0.0f, n0 = 0.0f, e1 = 0.0f, n1 = 0.0f, sjs = 0.0f;

    #pragma unroll
    for (int q = 0; q < 6; q++) {
        if (lane + q * 32 < nit) {
            unsigned prq = pr[q];
            #pragma unroll
            for (int half = 0; half < 2; half++) {
                int e = (half == 0) ? (prq & 0xFFFFu) : (prq >> 16);
                int j = e & 0xFFF;
                int m = e >> 12;
                float4 t4 = tab[m];           // (lut0', lut1', M, _)
                float sj = ss[j];
                float M  = t4.z;

                float x0 = fmaf(M, fmaf(b0, sj, c0), t4.x);
                x0 = fmaxf(x0, NEG * x0);     // lrelu commutes with log2e scale
                float v0 = ex2f(x0);
                e0 += v0; n0 = fmaf(v0, sj, n0);

                float x1 = fmaf(M, fmaf(b1, sj, c1), t4.y);
                x1 = fmaxf(x1, NEG * x1);
                float v1 = ex2f(x1);
                e1 += v1; n1 = fmaf(v1, sj, n1);

                sjs += sj;
            }
        }
    }

    #pragma unroll
    for (int o = 16; o; o >>= 1) {
        e0  += __shfl_xor_sync(0xFFFFFFFFu, e0,  o);
        n0  += __shfl_xor_sync(0xFFFFFFFFu, n0,  o);
        e1  += __shfl_xor_sync(0xFFFFFFFFu, e1,  o);
        n1  += __shfl_xor_sync(0xFFFFFFFFu, n1,  o);
        sjs += __shfl_xor_sync(0xFFFFFFFFu, sjs, o);
    }
    if (lane == 0) {
        float fc = (float)cnt;
        float r0 = (S + n0 - sjs) / ((float)NN + e0 - fc);
        float r1 = (S + n1 - sjs) / ((float)NN + e1 - fc);
        outp[row] = 0.5f * (r0 + r1);
    }

    // layer 0: last-retiring block reduces S1 (deterministic fixed-order tree)
    if (layer == 0) {
        __threadfence();
        __syncthreads();
        if (tid == 0) win = (atomicAdd(&g_ticket, 1u) == (unsigned)(gridDim.x - 1));
        __syncthreads();
        if (win) {
            if (tid == 0) g_ticket = 0;
            __threadfence();
            float p = __ldcg(&g_s1[tid]) + __ldcg(&g_s1[tid + 1024]) +
                      __ldcg(&g_s1[tid + 2048]) + __ldcg(&g_s1[tid + 3072]);
            #pragma unroll
            for (int o = 16; o; o >>= 1) p += __shfl_xor_sync(0xFFFFFFFFu, p, o);
            if (lane == 0) red[warp] = p;
            __syncthreads();
            if (tid < 32) {
                float v = red[tid];
                #pragma unroll
                for (int o = 16; o; o >>= 1) v += __shfl_xor_sync(0xFFFFFFFFu, v, o);
                if (tid == 0) g_S[1] = v;
            }
        }
    }
}

// ---------------------------------------------------------------- launch
extern "C" void kernel_launch(void* const* d_in, const int* in_sizes, int n_in,
                              void* d_out, int out_size) {
    const float* inputs     = (const float*)d_in[0];
    const float* lin_w      = (const float*)d_in[1];
    const float* lin_b      = (const float*)d_in[2];
    const float* edge_emb   = (const float*)d_in[3];
    const float* att_w      = (const float*)d_in[4];
    const int*   edge_lists = (const int*)  d_in[5];
    float* out = (float*)d_out;

    k_prep <<<PREP_BLKS, 256>>>(edge_lists, inputs, lin_w, lin_b, edge_emb, att_w);
    k_build<<<NN, 128>>>();
    k_pass <<<PASS_BLKS, 1024>>>(0, out);
    k_pass <<<PASS_BLKS, 1024>>>(1, out);
}

// round 7
// speedup vs baseline: 1.7239x; 1.7239x over previous
#include <cuda_runtime.h>

#define NN 4096
#define TT 3
#define DD 20
#define EE 131072      // 2^17
#define ATT_DIM 128
#define HEADS 2
#define LAYERS 2
#define WPR 128        // 32-bit words per bitmap row (4096/32)
#define NEG 0.2f
#define MAXDEG 384     // mean degree ~186; MAXDEG/2 = 6*32 u32 pairs
#define L2E 1.4426950408889634f

#define SCAT_BLKS 1536           // TT*EE / 256
#define SCORE_BLKS 512           // 4096 rows / 8 warps
#define PREP_BLKS (SCAT_BLKS + SCORE_BLKS + 1)
#define PASS_BLKS 128            // 32 rows/block, single wave

// ---- device scratch (static, allocation-free) ----
// interleaved bitmaps: [row][word][4] (lane 3 pad). Starts zeroed (.bss);
// k_pass0 re-zeroes after reading -> invariant holds across graph replays.
__device__ __align__(16) unsigned       g_bmi[NN * WPR * 4];   // 8MB
__device__ __align__(16) unsigned short g_ent[NN * MAXDEG];    // j | (m<<12)
__device__ int    g_cnt[NN];                                   // even (padded)
__device__ __align__(16) float g_s0[NN];
__device__ __align__(16) float g_s1[NN];
__device__ float4 g_tab[LAYERS][8];   // per-mask: (lut_h0', lut_h1', M, _)
__device__ float  g_ab[LAYERS][4];    // a0', b0', a1', b1' (log2e folded)

__device__ __forceinline__ float ex2f(float x) {
    float r;
    asm("ex2.approx.ftz.f32 %0, %1;" : "=f"(r) : "f"(x));
    return r;
}

// ----------------------- fused: edge scatter + initial scores + constants
__global__ void __launch_bounds__(256) k_prep(const int* __restrict__ el,
                                              const float* __restrict__ inputs,
                                              const float* __restrict__ lw,
                                              const float* __restrict__ lb,
                                              const float* __restrict__ edge_emb,
                                              const float* __restrict__ att_w) {
    int bid = blockIdx.x, tid = threadIdx.x;

    if (bid < SCAT_BLKS) {
        // ---- edge scatter: i < TT*EE
        int i = bid * 256 + tid;
        int t = i >> 17;               // EE = 2^17
        int e = i & (EE - 1);
        int s = el[(t * 2 + 0) * EE + e];
        int g = el[(t * 2 + 1) * EE + e];
        atomicOr(&g_bmi[(s * WPR + (g >> 5)) * 4 + t], 1u << (g & 31));
        atomicOr(&g_bmi[(g * WPR + (s >> 5)) * 4 + t], 1u << (s & 31));
    } else if (bid < SCAT_BLKS + SCORE_BLKS) {
        // ---- initial linear scores: one row per warp, 8 warps
        int warp = tid >> 5, lane = tid & 31;
        int row  = (bid - SCAT_BLKS) * 8 + warp;
        float4 v = reinterpret_cast<const float4*>(inputs + row * ATT_DIM)[lane];
        float4 w = reinterpret_cast<const float4*>(lw)[lane];
        float acc = v.x * w.x + v.y * w.y + v.z * w.z + v.w * w.w;
        #pragma unroll
        for (int o = 16; o; o >>= 1) acc += __shfl_xor_sync(0xFFFFFFFFu, acc, o);
        if (lane == 0) g_s0[row] = acc + lb[0];
    } else {
        // ---- per-(layer,head) constants
        float* tabf = reinterpret_cast<float*>(&g_tab[0][0]);
        if (tid < LAYERS * HEADS) {
            int l = tid >> 1, h = tid & 1;
            const float* w = att_w + (l * HEADS + h) * (DD + 2);
            float et[TT];
            #pragma unroll
            for (int t = 0; t < TT; t++) {
                float acc = 0.0f;
                #pragma unroll
                for (int d = 0; d < DD; d++) acc += edge_emb[t * DD + d] * w[1 + d];
                et[t] = acc * L2E;
            }
            g_ab[l][h * 2 + 0] = w[0] * L2E;
            g_ab[l][h * 2 + 1] = w[DD + 1] * L2E;
            #pragma unroll
            for (int m = 0; m < 8; m++) {
                float B = 0.0f;
                #pragma unroll
                for (int t = 0; t < TT; t++) if ((m >> t) & 1) B += et[t];
                tabf[(l * 8 + m) * 4 + h] = B;
            }
        } else if (tid < LAYERS * HEADS + 2) {
            int l = tid - LAYERS * HEADS;
            #pragma unroll
            for (int m = 0; m < 8; m++)
                tabf[(l * 8 + m) * 4 + 2] = (float)__popc((unsigned)m);
        }
    }
}

// ---------------- fused: CSR build (own 32 rows) + attention layer 0
// 128 blocks x 1024 threads; warp w owns row blk*32+w; lane handles 4 words.
__global__ void __launch_bounds__(1024) k_pass0() {
    __shared__ float  ss[NN];                       // 16KB scores
    __shared__ __align__(16) unsigned short se[32][MAXDEG];  // 24KB CSR rows
    __shared__ float4 tab[8];
    __shared__ float  ab[4];
    __shared__ float  red[32];
    __shared__ float  shS;

    int tid = threadIdx.x, warp = tid >> 5, lane = tid & 31;
    int row = blockIdx.x * 32 + warp;

    // ---- A: read this row's bitmap words (4 per lane, coalesced), zero-restore
    uint4* bmp = reinterpret_cast<uint4*>(&g_bmi[0]) + (size_t)row * WPR;
    uint4 wv0 = bmp[lane];
    uint4 wv1 = bmp[lane + 32];
    uint4 wv2 = bmp[lane + 64];
    uint4 wv3 = bmp[lane + 96];

    // ---- B: stage scores + S0 partials (overlaps bitmap scoreboard waits)
    float4 sv = __ldcg(reinterpret_cast<const float4*>(g_s0) + tid);
    reinterpret_cast<float4*>(ss)[tid] = sv;
    float part = (sv.x + sv.y) + (sv.z + sv.w);
    #pragma unroll
    for (int o = 16; o; o >>= 1) part += __shfl_xor_sync(0xFFFFFFFFu, part, o);
    if (lane == 0) red[warp] = part;
    if (tid < 8)       tab[tid]    = g_tab[0][tid];
    else if (tid < 12) ab[tid - 8] = g_ab[0][tid - 8];

    uint4 z = make_uint4(0u, 0u, 0u, 0u);
    bmp[lane] = z; bmp[lane + 32] = z; bmp[lane + 64] = z; bmp[lane + 96] = z;

    // ---- C: per-lane counts + warp scan
    unsigned u0 = wv0.x | wv0.y | wv0.z;
    unsigned u1 = wv1.x | wv1.y | wv1.z;
    unsigned u2 = wv2.x | wv2.y | wv2.z;
    unsigned u3 = wv3.x | wv3.y | wv3.z;
    int cnt = __popc(u0) + __popc(u1) + __popc(u2) + __popc(u3);

    int inc = cnt;
    #pragma unroll
    for (int o = 1; o < 32; o <<= 1) {
        int n = __shfl_up_sync(0xFFFFFFFFu, inc, o);
        if (lane >= o) inc += n;
    }
    int base = inc - cnt;
    int tot  = __shfl_sync(0xFFFFFFFFu, inc, 31);

    // ---- D: extract into this warp's smem CSR row
    unsigned short* sw = &se[warp][0];
    #pragma unroll
    for (int q = 0; q < 4; q++) {
        unsigned u  = (q == 0) ? u0 : (q == 1) ? u1 : (q == 2) ? u2 : u3;
        unsigned w0 = (q == 0) ? wv0.x : (q == 1) ? wv1.x : (q == 2) ? wv2.x : wv3.x;
        unsigned w1 = (q == 0) ? wv0.y : (q == 1) ? wv1.y : (q == 2) ? wv2.y : wv3.y;
        unsigned w2 = (q == 0) ? wv0.z : (q == 1) ? wv1.z : (q == 2) ? wv2.z : wv3.z;
        int col = (lane + 32 * q) * 32;
        while (u) {
            int b = __ffs(u) - 1;
            u &= u - 1;
            int m = ((w0 >> b) & 1) | (((w1 >> b) & 1) << 1) | (((w2 >> b) & 1) << 2);
            sw[base++] = (unsigned short)((col + b) | (m << 12));
        }
    }
    if (lane == 31 && (tot & 1)) sw[tot] = 0;   // pad entry (exact no-op)
    int cpad = (tot + 1) & ~1;
    if (lane == 0) g_cnt[row] = cpad;
    __syncwarp();

    // ---- E: stream entries to gmem for layer 1 (48 uint4, coalesced)
    {
        uint4* go = reinterpret_cast<uint4*>(&g_ent[row * MAXDEG]);
        const uint4* so = reinterpret_cast<const uint4*>(sw);
        go[lane] = so[lane];
        if (lane < 16) go[lane + 32] = so[lane + 32];
    }

    __syncthreads();                                 // ss + red ready
    if (tid < 32) {
        float v = red[tid];
        #pragma unroll
        for (int o = 16; o; o >>= 1) v += __shfl_xor_sync(0xFFFFFFFFu, v, o);
        if (tid == 0) shS = v;
    }
    __syncthreads();

    // ---- F: layer-0 attention, entries from smem
    float S  = shS;
    float si = ss[row];
    float a0 = ab[0], b0 = ab[1], a1 = ab[2], b1 = ab[3];
    float c0 = a0 * si, c1 = a1 * si;

    const unsigned* ep32 = reinterpret_cast<const unsigned*>(sw);
    int nit = cpad >> 1;
    float e0 = 0.0f, n0 = 0.0f, e1 = 0.0f, n1 = 0.0f, sjs = 0.0f;

    for (int k = lane; k < nit; k += 32) {
        unsigned pr = ep32[k];
        #pragma unroll
        for (int half = 0; half < 2; half++) {
            int e = (half == 0) ? (pr & 0xFFFFu) : (pr >> 16);
            int j = e & 0xFFF;
            int m = e >> 12;
            float4 t4 = tab[m];           // (lut0', lut1', M, _)
            float sj = ss[j];
            float M  = t4.z;

            float x0 = fmaf(M, fmaf(b0, sj, c0), t4.x);
            x0 = fmaxf(x0, NEG * x0);     // lrelu commutes with log2e scale
            float v0 = ex2f(x0);
            e0 += v0; n0 = fmaf(v0, sj, n0);

            float x1 = fmaf(M, fmaf(b1, sj, c1), t4.y);
            x1 = fmaxf(x1, NEG * x1);
            float v1 = ex2f(x1);
            e1 += v1; n1 = fmaf(v1, sj, n1);

            sjs += sj;
        }
    }

    #pragma unroll
    for (int o = 16; o; o >>= 1) {
        e0  += __shfl_xor_sync(0xFFFFFFFFu, e0,  o);
        n0  += __shfl_xor_sync(0xFFFFFFFFu, n0,  o);
        e1  += __shfl_xor_sync(0xFFFFFFFFu, e1,  o);
        n1  += __shfl_xor_sync(0xFFFFFFFFu, n1,  o);
        sjs += __shfl_xor_sync(0xFFFFFFFFu, sjs, o);
    }
    if (lane == 0) {
        float fc = (float)cpad;
        float r0 = (S + n0 - sjs) / ((float)NN + e0 - fc);
        float r1 = (S + n1 - sjs) / ((float)NN + e1 - fc);
        g_s1[row] = 0.5f * (r0 + r1);
    }
}

// ------------------------------------- layer-1 attention (entries L2-warm)
__global__ void __launch_bounds__(1024) k_pass1(float* __restrict__ out) {
    __shared__ float  ss[NN];
    __shared__ float4 tab[8];
    __shared__ float  ab[4];
    __shared__ float  red[32];
    __shared__ float  shS;

    int tid = threadIdx.x, warp = tid >> 5, lane = tid & 31;
    int row = blockIdx.x * 32 + warp;

    int cnt = g_cnt[row];
    const unsigned* __restrict__ ep32 =
        reinterpret_cast<const unsigned*>(&g_ent[row * MAXDEG]);
    unsigned pr[6];
    #pragma unroll
    for (int q = 0; q < 6; q++) pr[q] = ep32[lane + q * 32];   // MLP=6

    float4 sv = __ldcg(reinterpret_cast<const float4*>(g_s1) + tid);
    reinterpret_cast<float4*>(ss)[tid] = sv;
    float part = (sv.x + sv.y) + (sv.z + sv.w);
    #pragma unroll
    for (int o = 16; o; o >>= 1) part += __shfl_xor_sync(0xFFFFFFFFu, part, o);
    if (lane == 0) red[warp] = part;
    if (tid < 8)       tab[tid]    = g_tab[1][tid];
    else if (tid < 12) ab[tid - 8] = g_ab[1][tid - 8];
    __syncthreads();

    if (tid < 32) {
        float v = red[tid];
        #pragma unroll
        for (int o = 16; o; o >>= 1) v += __shfl_xor_sync(0xFFFFFFFFu, v, o);
        if (tid == 0) shS = v;
    }
    __syncthreads();

    float S  = shS;
    float si = ss[row];
    float a0 = ab[0], b0 = ab[1], a1 = ab[2], b1 = ab[3];
    float c0 = a0 * si, c1 = a1 * si;

    int nit = cnt >> 1;
    float e0 = 0.0f, n0 = 0.0f, e1 = 0.0f, n1 = 0.0f, sjs = 0.0f;

    #pragma unroll
    for (int q = 0; q < 6; q++) {
        if (lane + q * 32 < nit) {
            unsigned prq = pr[q];
            #pragma unroll
            for (int half = 0; half < 2; half++) {
                int e = (half == 0) ? (prq & 0xFFFFu) : (prq >> 16);
                int j = e & 0xFFF;
                int m = e >> 12;
                float4 t4 = tab[m];
                float sj = ss[j];
                float M  = t4.z;

                float x0 = fmaf(M, fmaf(b0, sj, c0), t4.x);
                x0 = fmaxf(x0, NEG * x0);
                float v0 = ex2f(x0);
                e0 += v0; n0 = fmaf(v0, sj, n0);

                float x1 = fmaf(M, fmaf(b1, sj, c1), t4.y);
                x1 = fmaxf(x1, NEG * x1);
                float v1 = ex2f(x1);
                e1 += v1; n1 = fmaf(v1, sj, n1);

                sjs += sj;
            }
        }
    }

    #pragma unroll
    for (int o = 16; o; o >>= 1) {
        e0  += __shfl_xor_sync(0xFFFFFFFFu, e0,  o);
        n0  += __shfl_xor_sync(0xFFFFFFFFu, n0,  o);
        e1  += __shfl_xor_sync(0xFFFFFFFFu, e1,  o);
        n1  += __shfl_xor_sync(0xFFFFFFFFu, n1,  o);
        sjs += __shfl_xor_sync(0xFFFFFFFFu, sjs, o);
    }
    if (lane == 0) {
        float fc = (float)cnt;
        float r0 = (S + n0 - sjs) / ((float)NN + e0 - fc);
        float r1 = (S + n1 - sjs) / ((float)NN + e1 - fc);
        out[row] = 0.5f * (r0 + r1);
    }
}

// ---------------------------------------------------------------- launch
extern "C" void kernel_launch(void* const* d_in, const int* in_sizes, int n_in,
                              void* d_out, int out_size) {
    const float* inputs     = (const float*)d_in[0];
    const float* lin_w      = (const float*)d_in[1];
    const float* lin_b      = (const float*)d_in[2];
    const float* edge_emb   = (const float*)d_in[3];
    const float* att_w      = (const float*)d_in[4];
    const int*   edge_lists = (const int*)  d_in[5];
    float* out = (float*)d_out;

    k_prep <<<PREP_BLKS, 256>>>(edge_lists, inputs, lin_w, lin_b, edge_emb, att_w);
    k_pass0<<<PASS_BLKS, 1024>>>();
    k_pass1<<<PASS_BLKS, 1024>>>(out);
}